// round 12
// baseline (speedup 1.0000x reference)
#include <cuda_runtime.h>
#include <cuda_fp16.h>
#include <cstdint>

// ============================================================================
// QuantizedLinear: out[1024,4096] = x @ W^T + bias
//   W[o, b*8+j] = centroids[assignments[b*4096 + o], j]
//
// fp16 mma.sync.m16n8k16 (f32 accum). R12 = R8 + fp16 pre-converted centroid
// table: W-pass random gathers become 2x LDG.128 (32B) per iteration instead
// of 4x (64B) with no cvts, halving the L1 gather/replay cost. GEMM is the
// R8/R6 core, pinned at the ~12 cyc/HMMA/SMSP legacy-mma floor.
// ============================================================================

#define M_DIM 1024
#define N_DIM 4096
#define K_DIM 4096
#define BM 128
#define BN 128
#define BK 64                            // 64 k per tile -> 128B fp16 rows
#define STAGES 2
#define NT (K_DIM / BK)                  // 64 k-tiles
#define A_BYTES (BM * 128)               // 16384
#define B_BYTES (BN * 128)               // 16384
#define STAGE_BYTES (A_BYTES + B_BYTES)  // 32768
#define SMEM_TOTAL (STAGES * STAGE_BYTES) // 65536
#define THREADS 128
#define NCENT 2048

// fp16 operands, fragment-friendly permuted layout: row-major [row][K]; each
// 16-k block stored in order {0,1,8,9,2,3,10,11, 4,5,12,13,6,7,14,15}.
__device__ __align__(16) __half g_Ap[(size_t)M_DIM * K_DIM];
__device__ __align__(16) __half g_Bp[(size_t)N_DIM * K_DIM];
__device__ __align__(16) __half g_tab[NCENT * 8];   // fp16 centroid table, 32KB

// ---------------------------------------------------------------------------
__device__ __forceinline__ uint32_t smem_u32(const void* p) {
    uint32_t a;
    asm("{ .reg .u64 t; cvta.to.shared.u64 t, %1; cvt.u32.u64 %0, t; }"
        : "=r"(a) : "l"(p));
    return a;
}

__device__ __forceinline__ void cp_async16(uint32_t s, const void* g) {
    asm volatile("cp.async.cg.shared.global [%0], [%1], 16;" :: "r"(s), "l"(g));
}
#define CP_COMMIT() asm volatile("cp.async.commit_group;" ::: "memory")
#define CP_WAIT0()  asm volatile("cp.async.wait_group 0;" ::: "memory")

__device__ __forceinline__ void mma_f16(float* c, const uint32_t* a, const uint32_t* b) {
    asm volatile(
        "mma.sync.aligned.m16n8k16.row.col.f32.f16.f16.f32 "
        "{%0,%1,%2,%3}, {%4,%5,%6,%7}, {%8,%9}, {%0,%1,%2,%3};"
        : "+f"(c[0]), "+f"(c[1]), "+f"(c[2]), "+f"(c[3])
        : "r"(a[0]), "r"(a[1]), "r"(a[2]), "r"(a[3]), "r"(b[0]), "r"(b[1]));
}

// ---------------------------------------------------------------------------
// Kernel 0: convert centroid table to fp16 (2048 rows x 8 -> 16B each).
// ---------------------------------------------------------------------------
__global__ void __launch_bounds__(256) conv_tab_kernel(const float* __restrict__ cent) {
    int r = blockIdx.x * 256 + threadIdx.x;      // 2048 rows, grid 8
    float4 lo = __ldg(reinterpret_cast<const float4*>(cent + (size_t)r * 8));
    float4 hi = __ldg(reinterpret_cast<const float4*>(cent + (size_t)r * 8 + 4));
    __half2 h[4];
    h[0] = __floats2half2_rn(lo.x, lo.y);        // k0,k1
    h[1] = __floats2half2_rn(lo.z, lo.w);        // k2,k3
    h[2] = __floats2half2_rn(hi.x, hi.y);        // k4,k5
    h[3] = __floats2half2_rn(hi.z, hi.w);        // k6,k7
    *reinterpret_cast<uint4*>(g_tab + r * 8) = *reinterpret_cast<uint4*>(h);
}

// ---------------------------------------------------------------------------
// Prep (3072 blocks of 256):
//   blocks [0,1024):    x -> g_Ap. One thread = one 16-k block:
//                       4x LDG.128 -> 2x STG.128 permuted fp16.
//   blocks [1024,3072): dequant W -> g_Bp via fp16 table (2x LDG.128 per
//                       chunk-pair, no cvt). Block covers 64 n x 128 K.
// ---------------------------------------------------------------------------
__global__ void __launch_bounds__(256) prep_kernel(const float* __restrict__ x,
                                                   const int* __restrict__ assign) {
    __shared__ int s_cid[16 * 64];
    const int b = blockIdx.x;
    const int tid = threadIdx.x;

    if (b < 1024) {
        int g = b * 256 + tid;                // 16-k block index
        int m = g >> 8;                       // 256 blocks per row
        int kb = g & 255;
        const float4* src = reinterpret_cast<const float4*>(
            x + (size_t)m * K_DIM + kb * 16);
        float4 f0 = __ldg(src + 0);   // k0..3
        float4 f1 = __ldg(src + 1);   // k4..7
        float4 f2 = __ldg(src + 2);   // k8..11
        float4 f3 = __ldg(src + 3);   // k12..15
        __half2 o0[4], o1[4];
        o0[0] = __floats2half2_rn(f0.x, f0.y);
        o0[1] = __floats2half2_rn(f2.x, f2.y);
        o0[2] = __floats2half2_rn(f0.z, f0.w);
        o0[3] = __floats2half2_rn(f2.z, f2.w);
        o1[0] = __floats2half2_rn(f1.x, f1.y);
        o1[1] = __floats2half2_rn(f3.x, f3.y);
        o1[2] = __floats2half2_rn(f1.z, f1.w);
        o1[3] = __floats2half2_rn(f3.z, f3.w);
        uint4* dst = reinterpret_cast<uint4*>(g_Ap + (size_t)g * 16);
        dst[0] = *reinterpret_cast<uint4*>(o0);
        dst[1] = *reinterpret_cast<uint4*>(o1);
    } else {
        const int wb = b - 1024;              // 0..2047
        const int n0 = (wb & 63) * 64;        // 64 out-features per block
        const int kb0 = (wb >> 6) * 128;      // 128 K per block
        const int b0 = kb0 >> 3;              // first of 16 in-blocks
#pragma unroll
        for (int i = 0; i < 4; i++) {
            int idx = tid + i * 256;
            int bl = idx >> 6, nl = idx & 63;
            s_cid[bl * 64 + nl] = assign[(size_t)(b0 + bl) * N_DIM + n0 + nl];
        }
        __syncthreads();

        // 1024 chunk-pairs: thread does chunks (2t16, 2t16+1) of one n-row.
        // fp16 row uint4: x=(k0,k1) y=(k2,k3) z=(k4,k5) w=(k6,k7).
        // chunk h0 = {r0.x, r1.x, r0.y, r1.y}; chunk h1 = {r0.z, r1.z, r0.w, r1.w}
#pragma unroll
        for (int i = 0; i < 4; i++) {
            int l = tid + i * 256;            // 1024: 64 rows x 16 chunks -> pairs
            int nl = l >> 3;                  // 8 chunk-pairs per n-row? no:
            int t16 = l & 7;                  // 8 pairs (16 chunks) per row? ->
            // 64 rows x 8 pairs = 512... need 1024 iter over 64 rows x 16 t16?
            // Correction: 16 chunks per row = 8 pairs; 64*8=512 pairs, but we
            // have 1024 slots -> each thread-slot does one pair, 2 i-iters
            // cover all. Keep 4 iters but split: use l<512 guard-free mapping:
            nl = l >> 4;                      // 64 rows (l in [0,1024))
            t16 = l & 15;                     // t16 0..15? only 8 pairs exist.
            // Map l in [0,1024): rows 0..63, each with 16 half-pairs ->
            // treat t16 as chunk index c (0..15), handle ONE chunk per iter.
            int c = t16;
            int tb = c >> 1;                  // 16-k block within 128K: 0..7
            int h = c & 1;
            int cid0 = s_cid[(2 * tb) * 64 + nl];
            int cid1 = s_cid[(2 * tb + 1) * 64 + nl];
            uint4 r0 = *reinterpret_cast<const uint4*>(g_tab + cid0 * 8);
            uint4 r1 = *reinterpret_cast<const uint4*>(g_tab + cid1 * 8);
            uint4 o = h ? make_uint4(r0.z, r1.z, r0.w, r1.w)
                        : make_uint4(r0.x, r1.x, r0.y, r1.y);
            *reinterpret_cast<uint4*>(
                g_Bp + (size_t)(n0 + nl) * K_DIM + kb0 + c * 8) = o;
        }
    }
}

// ---------------------------------------------------------------------------
// GEMM (identical to R8): grid (32, 8), 128 threads, warp grid 2(m) x 2(n),
// warp tile 64x64, 2-stage cp.async pipeline, 2 CTAs/SM.
// Smem tile rows 128B; 16B-chunk swizzle: c ^= (row&3)*2.
// ---------------------------------------------------------------------------
__device__ __forceinline__ void load_tile(uint32_t smem_base, int stage,
                                          const __half* __restrict__ Ab,
                                          const __half* __restrict__ Bb,
                                          int kt, int tid) {
    uint32_t sA = smem_base + stage * STAGE_BYTES;
    uint32_t sB = sA + A_BYTES;
    const __half* Ag = Ab + kt * BK;
    const __half* Bg = Bb + kt * BK;
#pragma unroll
    for (int i = 0; i < 8; i++) {            // A: 1024 16B chunks
        int c = tid + i * THREADS;
        int row = c >> 3, ck = c & 7;
        uint32_t dst = sA + row * 128 + (uint32_t)((ck ^ ((row & 3) * 2)) << 4);
        cp_async16(dst, Ag + (size_t)row * K_DIM + ck * 8);
    }
#pragma unroll
    for (int i = 0; i < 8; i++) {            // B: 1024 16B chunks
        int c = tid + i * THREADS;
        int row = c >> 3, ck = c & 7;
        uint32_t dst = sB + row * 128 + (uint32_t)((ck ^ ((row & 3) * 2)) << 4);
        cp_async16(dst, Bg + (size_t)row * K_DIM + ck * 8);
    }
}

__global__ void __launch_bounds__(THREADS, 2)
gemm_kernel(const float* __restrict__ bias, float* __restrict__ out) {
    extern __shared__ char dsm[];
    const uint32_t smem_base = smem_u32(dsm);
    const int tid = threadIdx.x;
    const int lane = tid & 31;
    const int wid = tid >> 5;                // 0..3
    const int gid = lane >> 2;               // 0..7
    const int tig = lane & 3;                // 0..3
    const int wm0 = (wid >> 1) * 64;         // 2 m-slots of 64
    const int wn0 = (wid & 1) * 64;          // 2 n-slots of 64
    const int m0 = blockIdx.y * BM;
    const int n0 = blockIdx.x * BN;

    const __half* Ab = g_Ap + (size_t)m0 * K_DIM;
    const __half* Bb = g_Bp + (size_t)n0 * K_DIM;

    float acc[4][8][4];
#pragma unroll
    for (int mt = 0; mt < 4; mt++)
#pragma unroll
        for (int nt = 0; nt < 8; nt++)
#pragma unroll
            for (int r = 0; r < 4; r++) acc[mt][nt][r] = 0.0f;

    const uint32_t swz_x = (uint32_t)((gid & 3) * 2);
    const uint32_t sub8 = (uint32_t)((tig & 1) << 3);

    // Fragment double buffers (per 16-k block)
    uint32_t af[2][4][4];
    uint32_t bf[2][8][2];

    #define FRAG_LOAD(B, sa, sb, kbl)                                          \
    do {                                                                       \
        const uint32_t coff =                                                  \
            (uint32_t)(((((kbl) * 2 + (tig >> 1)) ^ swz_x) << 4) | sub8);      \
        _Pragma("unroll")                                                      \
        for (int mt = 0; mt < 4; mt++) {                                       \
            int rlo = wm0 + mt * 16 + gid;                                     \
            uint2 lo = *reinterpret_cast<const uint2*>((sa) + rlo * 128 + coff); \
            uint2 hi = *reinterpret_cast<const uint2*>((sa) + (rlo + 8) * 128 + coff); \
            af[B][mt][0] = lo.x; af[B][mt][2] = lo.y;                          \
            af[B][mt][1] = hi.x; af[B][mt][3] = hi.y;                          \
        }                                                                      \
        _Pragma("unroll")                                                      \
        for (int nt = 0; nt < 8; nt++) {                                       \
            int r = wn0 + nt * 8 + gid;                                        \
            uint2 v = *reinterpret_cast<const uint2*>((sb) + r * 128 + coff);  \
            bf[B][nt][0] = v.x; bf[B][nt][1] = v.y;                            \
        }                                                                      \
    } while (0)

    // Prologue: stage 0 <- tile 0
    load_tile(smem_base, 0, Ab, Bb, 0, tid);
    CP_COMMIT();

    for (int kt = 0; kt < NT; kt++) {
        CP_WAIT0();                          // tile kt resident
        __syncthreads();                     // all warps done with other stage

        if (kt + 1 < NT) {                   // load next tile into freed stage
            load_tile(smem_base, (kt + 1) & 1, Ab, Bb, kt + 1, tid);
            CP_COMMIT();
        }

        const char* sa = dsm + (kt & 1) * STAGE_BYTES;
        const char* sb = sa + A_BYTES;

        FRAG_LOAD(0, sa, sb, 0);             // warm kb0
#pragma unroll
        for (int kb = 0; kb < 4; kb++) {     // four 16-k blocks
            if (kb < 3) FRAG_LOAD((kb + 1) & 1, sa, sb, kb + 1);
            const int B = kb & 1;
#pragma unroll
            for (int mt = 0; mt < 4; mt++)
#pragma unroll
                for (int nt = 0; nt < 8; nt++)
                    mma_f16(acc[mt][nt], af[B][mt], bf[B][nt]);
        }
    }

    // Epilogue: c0,c1 -> (row gid, cols tig*2,+1); c2,c3 -> row gid+8.
#pragma unroll
    for (int mt = 0; mt < 4; mt++) {
        int mlo = m0 + wm0 + mt * 16 + gid;
#pragma unroll
        for (int nt = 0; nt < 8; nt++) {
            int n = n0 + wn0 + nt * 8 + tig * 2;
            float bx = __ldg(bias + n);
            float by = __ldg(bias + n + 1);
            float2 v0 = {acc[mt][nt][0] + bx, acc[mt][nt][1] + by};
            float2 v1 = {acc[mt][nt][2] + bx, acc[mt][nt][3] + by};
            *reinterpret_cast<float2*>(out + (size_t)mlo * N_DIM + n) = v0;
            *reinterpret_cast<float2*>(out + (size_t)(mlo + 8) * N_DIM + n) = v1;
        }
    }
}

// ---------------------------------------------------------------------------
extern "C" void kernel_launch(void* const* d_in, const int* in_sizes, int n_in,
                              void* d_out, int out_size) {
    const float* x = nullptr;
    const float* cent = nullptr;
    const float* bias = nullptr;
    const int* assign = nullptr;
    // Inputs by element count: x=4194304, centroids=16384, bias=4096,
    // assignments=2097152, counts=2048 (unused).
    for (int i = 0; i < n_in; i++) {
        switch (in_sizes[i]) {
            case M_DIM * K_DIM:        x = (const float*)d_in[i]; break;
            case 2048 * 8:             cent = (const float*)d_in[i]; break;
            case N_DIM:                bias = (const float*)d_in[i]; break;
            case (K_DIM / 8) * N_DIM:  assign = (const int*)d_in[i]; break;
            default: break;
        }
    }

    static bool attr_done = false;
    if (!attr_done) {
        cudaFuncSetAttribute(gemm_kernel,
                             cudaFuncAttributeMaxDynamicSharedMemorySize, SMEM_TOTAL);
        attr_done = true;
    }

    conv_tab_kernel<<<NCENT / 256, 256>>>(cent);
    prep_kernel<<<3072, 256>>>(x, assign);
    gemm_kernel<<<dim3(N_DIM / BN, M_DIM / BM), THREADS, SMEM_TOTAL>>>(
        bias, (float*)d_out);
}

// round 13
// speedup vs baseline: 1.1353x; 1.1353x over previous
#include <cuda_runtime.h>
#include <cuda_fp16.h>
#include <cstdint>

// ============================================================================
// QuantizedLinear: out[1024,4096] = x @ W^T + bias
//   W[o, b*8+j] = centroids[assignments[b*4096 + o], j]
//
// fp16 mma.sync.m16n8k16 (f32 accum). R13: BN=112 tiles -> 37x8 = 296 CTAs
// = exactly 2 per SM on ALL 148 SMs. Busiest-SM HMMA drops 65536 -> 57344
// (-12.5%), breaking the power-of-2 quantization that pinned the GEMM at
// 97.7us. Prep = R8's (single launch, at its wavefront-bound floor).
// ============================================================================

#define M_DIM 1024
#define N_DIM 4096
#define K_DIM 4096
#define BM 128
#define BN 112                           // 14 n8-frags; 37 tiles cover N
#define NTILE_N 37
#define N_PAD (NTILE_N * BN)             // 4144 rows in g_Bp (pad zero)
#define BK 64                            // 64 k per tile -> 128B fp16 rows
#define STAGES 2
#define NT (K_DIM / BK)                  // 64 k-tiles
#define A_BYTES (BM * 128)               // 16384
#define B_BYTES (BN * 128)               // 14336
#define STAGE_BYTES (A_BYTES + B_BYTES)  // 30720
#define SMEM_TOTAL (STAGES * STAGE_BYTES) // 61440
#define THREADS 128

// fp16 operands, fragment-friendly permuted layout: row-major [row][K]; each
// 16-k block stored in order {0,1,8,9,2,3,10,11, 4,5,12,13,6,7,14,15}.
// g_Bp padded to N_PAD rows; rows >= 4096 stay zero (static zero-init, never
// written) so the last tile's OOB columns are harmless.
__device__ __align__(16) __half g_Ap[(size_t)M_DIM * K_DIM];
__device__ __align__(16) __half g_Bp[(size_t)N_PAD * K_DIM];

// ---------------------------------------------------------------------------
__device__ __forceinline__ uint32_t smem_u32(const void* p) {
    uint32_t a;
    asm("{ .reg .u64 t; cvta.to.shared.u64 t, %1; cvt.u32.u64 %0, t; }"
        : "=r"(a) : "l"(p));
    return a;
}

__device__ __forceinline__ void cp_async16(uint32_t s, const void* g) {
    asm volatile("cp.async.cg.shared.global [%0], [%1], 16;" :: "r"(s), "l"(g));
}
#define CP_COMMIT() asm volatile("cp.async.commit_group;" ::: "memory")
#define CP_WAIT0()  asm volatile("cp.async.wait_group 0;" ::: "memory")

__device__ __forceinline__ void mma_f16(float* c, const uint32_t* a, const uint32_t* b) {
    asm volatile(
        "mma.sync.aligned.m16n8k16.row.col.f32.f16.f16.f32 "
        "{%0,%1,%2,%3}, {%4,%5,%6,%7}, {%8,%9}, {%0,%1,%2,%3};"
        : "+f"(c[0]), "+f"(c[1]), "+f"(c[2]), "+f"(c[3])
        : "r"(a[0]), "r"(a[1]), "r"(a[2]), "r"(a[3]), "r"(b[0]), "r"(b[1]));
}

// ---------------------------------------------------------------------------
// Prep (3072 blocks of 256) — identical to R8:
//   blocks [0,1024):    x -> g_Ap. One thread = one 16-k block:
//                       4x LDG.128 -> 2x STG.128 permuted fp16.
//   blocks [1024,3072): dequant W -> g_Bp via 2x LDG.128 centroid halves.
// ---------------------------------------------------------------------------
__global__ void __launch_bounds__(256) prep_kernel(const float* __restrict__ x,
                                                   const int* __restrict__ assign,
                                                   const float* __restrict__ cent) {
    __shared__ int s_cid[16 * 64];
    const int b = blockIdx.x;
    const int tid = threadIdx.x;

    if (b < 1024) {
        int g = b * 256 + tid;                // 16-k block index
        int m = g >> 8;                       // 256 blocks per row
        int kb = g & 255;
        const float4* src = reinterpret_cast<const float4*>(
            x + (size_t)m * K_DIM + kb * 16);
        float4 f0 = __ldg(src + 0);   // k0..3
        float4 f1 = __ldg(src + 1);   // k4..7
        float4 f2 = __ldg(src + 2);   // k8..11
        float4 f3 = __ldg(src + 3);   // k12..15
        __half2 o0[4], o1[4];
        o0[0] = __floats2half2_rn(f0.x, f0.y);
        o0[1] = __floats2half2_rn(f2.x, f2.y);
        o0[2] = __floats2half2_rn(f0.z, f0.w);
        o0[3] = __floats2half2_rn(f2.z, f2.w);
        o1[0] = __floats2half2_rn(f1.x, f1.y);
        o1[1] = __floats2half2_rn(f3.x, f3.y);
        o1[2] = __floats2half2_rn(f1.z, f1.w);
        o1[3] = __floats2half2_rn(f3.z, f3.w);
        uint4* dst = reinterpret_cast<uint4*>(g_Ap + (size_t)g * 16);
        dst[0] = *reinterpret_cast<uint4*>(o0);
        dst[1] = *reinterpret_cast<uint4*>(o1);
    } else {
        const int wb = b - 1024;              // 0..2047
        const int n0 = (wb & 63) * 64;        // 64 out-features per block
        const int kb0 = (wb >> 6) * 128;      // 128 K per block
        const int b0 = kb0 >> 3;              // first of 16 in-blocks
#pragma unroll
        for (int i = 0; i < 4; i++) {
            int idx = tid + i * 256;
            int bl = idx >> 6, nl = idx & 63;
            s_cid[bl * 64 + nl] = assign[(size_t)(b0 + bl) * N_DIM + n0 + nl];
        }
        __syncthreads();

        // Chunk c (0..15): t16=c>>1, half=c&1.
        //   half 0 holds ks {0,1,8,9,2,3,10,11}; half 1 ks {4,5,12,13,6,7,14,15}
#pragma unroll
        for (int i = 0; i < 4; i++) {
            int l = tid + i * 256;
            int nl = l >> 4;
            int c = l & 15;
            int t16 = c >> 1;
            int half = c & 1;
            int cid0 = s_cid[(2 * t16) * 64 + nl];
            int cid1 = s_cid[(2 * t16 + 1) * 64 + nl];
            float4 v0 = __ldg(reinterpret_cast<const float4*>(
                cent + (size_t)cid0 * 8 + half * 4));
            float4 v1 = __ldg(reinterpret_cast<const float4*>(
                cent + (size_t)cid1 * 8 + half * 4));
            __half2 o[4];
            o[0] = __floats2half2_rn(v0.x, v0.y);
            o[1] = __floats2half2_rn(v1.x, v1.y);
            o[2] = __floats2half2_rn(v0.z, v0.w);
            o[3] = __floats2half2_rn(v1.z, v1.w);
            *reinterpret_cast<uint4*>(
                g_Bp + (size_t)(n0 + nl) * K_DIM + kb0 + c * 8) =
                *reinterpret_cast<uint4*>(o);
        }
    }
}

// ---------------------------------------------------------------------------
// GEMM: grid (37, 8) = 296 CTAs (2/SM on all 148 SMs), 128 threads,
// warp grid 2(m) x 2(n), warp tile 64x56, 2-stage cp.async pipeline.
// Smem tile rows 128B; 16B-chunk swizzle: c ^= (row&3)*2.
// ---------------------------------------------------------------------------
__device__ __forceinline__ void load_tile(uint32_t smem_base, int stage,
                                          const __half* __restrict__ Ab,
                                          const __half* __restrict__ Bb,
                                          int kt, int tid) {
    uint32_t sA = smem_base + stage * STAGE_BYTES;
    uint32_t sB = sA + A_BYTES;
    const __half* Ag = Ab + kt * BK;
    const __half* Bg = Bb + kt * BK;
#pragma unroll
    for (int i = 0; i < 8; i++) {            // A: 1024 16B chunks
        int c = tid + i * THREADS;
        int row = c >> 3, ck = c & 7;
        uint32_t dst = sA + row * 128 + (uint32_t)((ck ^ ((row & 3) * 2)) << 4);
        cp_async16(dst, Ag + (size_t)row * K_DIM + ck * 8);
    }
#pragma unroll
    for (int i = 0; i < 7; i++) {            // B: 896 16B chunks (112 rows)
        int c = tid + i * THREADS;
        int row = c >> 3, ck = c & 7;
        uint32_t dst = sB + row * 128 + (uint32_t)((ck ^ ((row & 3) * 2)) << 4);
        cp_async16(dst, Bg + (size_t)row * K_DIM + ck * 8);
    }
}

__global__ void __launch_bounds__(THREADS, 2)
gemm_kernel(const float* __restrict__ bias, float* __restrict__ out) {
    extern __shared__ char dsm[];
    const uint32_t smem_base = smem_u32(dsm);
    const int tid = threadIdx.x;
    const int lane = tid & 31;
    const int wid = tid >> 5;                // 0..3
    const int gid = lane >> 2;               // 0..7
    const int tig = lane & 3;                // 0..3
    const int wm0 = (wid >> 1) * 64;         // 2 m-slots of 64
    const int wn0 = (wid & 1) * 56;          // 2 n-slots of 56
    const int m0 = blockIdx.y * BM;
    const int n0 = blockIdx.x * BN;

    const __half* Ab = g_Ap + (size_t)m0 * K_DIM;
    const __half* Bb = g_Bp + (size_t)n0 * K_DIM;

    float acc[4][7][4];
#pragma unroll
    for (int mt = 0; mt < 4; mt++)
#pragma unroll
        for (int nt = 0; nt < 7; nt++)
#pragma unroll
            for (int r = 0; r < 4; r++) acc[mt][nt][r] = 0.0f;

    const uint32_t swz_x = (uint32_t)((gid & 3) * 2);
    const uint32_t sub8 = (uint32_t)((tig & 1) << 3);

    // Fragment double buffers (per 16-k block)
    uint32_t af[2][4][4];
    uint32_t bf[2][7][2];

    #define FRAG_LOAD(B, sa, sb, kbl)                                          \
    do {                                                                       \
        const uint32_t coff =                                                  \
            (uint32_t)(((((kbl) * 2 + (tig >> 1)) ^ swz_x) << 4) | sub8);      \
        _Pragma("unroll")                                                      \
        for (int mt = 0; mt < 4; mt++) {                                       \
            int rlo = wm0 + mt * 16 + gid;                                     \
            uint2 lo = *reinterpret_cast<const uint2*>((sa) + rlo * 128 + coff); \
            uint2 hi = *reinterpret_cast<const uint2*>((sa) + (rlo + 8) * 128 + coff); \
            af[B][mt][0] = lo.x; af[B][mt][2] = lo.y;                          \
            af[B][mt][1] = hi.x; af[B][mt][3] = hi.y;                          \
        }                                                                      \
        _Pragma("unroll")                                                      \
        for (int nt = 0; nt < 7; nt++) {                                       \
            int r = wn0 + nt * 8 + gid;                                        \
            uint2 v = *reinterpret_cast<const uint2*>((sb) + r * 128 + coff);  \
            bf[B][nt][0] = v.x; bf[B][nt][1] = v.y;                            \
        }                                                                      \
    } while (0)

    // Prologue: stage 0 <- tile 0
    load_tile(smem_base, 0, Ab, Bb, 0, tid);
    CP_COMMIT();

    for (int kt = 0; kt < NT; kt++) {
        CP_WAIT0();                          // tile kt resident
        __syncthreads();                     // all warps done with other stage

        if (kt + 1 < NT) {                   // load next tile into freed stage
            load_tile(smem_base, (kt + 1) & 1, Ab, Bb, kt + 1, tid);
            CP_COMMIT();
        }

        const char* sa = dsm + (kt & 1) * STAGE_BYTES;
        const char* sb = sa + A_BYTES;

        FRAG_LOAD(0, sa, sb, 0);             // warm kb0
#pragma unroll
        for (int kb = 0; kb < 4; kb++) {     // four 16-k blocks
            if (kb < 3) FRAG_LOAD((kb + 1) & 1, sa, sb, kb + 1);
            const int B = kb & 1;
#pragma unroll
            for (int mt = 0; mt < 4; mt++)
#pragma unroll
                for (int nt = 0; nt < 7; nt++)
                    mma_f16(acc[mt][nt], af[B][mt], bf[B][nt]);
        }
    }

    // Epilogue: c0,c1 -> (row gid, cols tig*2,+1); c2,c3 -> row gid+8.
    // Guard n < N_DIM (last n-tile covers columns 4032..4143).
#pragma unroll
    for (int mt = 0; mt < 4; mt++) {
        int mlo = m0 + wm0 + mt * 16 + gid;
#pragma unroll
        for (int nt = 0; nt < 7; nt++) {
            int n = n0 + wn0 + nt * 8 + tig * 2;
            if (n < N_DIM) {
                float bx = __ldg(bias + n);
                float by = __ldg(bias + n + 1);
                float2 v0 = {acc[mt][nt][0] + bx, acc[mt][nt][1] + by};
                float2 v1 = {acc[mt][nt][2] + bx, acc[mt][nt][3] + by};
                *reinterpret_cast<float2*>(out + (size_t)mlo * N_DIM + n) = v0;
                *reinterpret_cast<float2*>(out + (size_t)(mlo + 8) * N_DIM + n) = v1;
            }
        }
    }
}

// ---------------------------------------------------------------------------
extern "C" void kernel_launch(void* const* d_in, const int* in_sizes, int n_in,
                              void* d_out, int out_size) {
    const float* x = nullptr;
    const float* cent = nullptr;
    const float* bias = nullptr;
    const int* assign = nullptr;
    // Inputs by element count: x=4194304, centroids=16384, bias=4096,
    // assignments=2097152, counts=2048 (unused).
    for (int i = 0; i < n_in; i++) {
        switch (in_sizes[i]) {
            case M_DIM * K_DIM:        x = (const float*)d_in[i]; break;
            case 2048 * 8:             cent = (const float*)d_in[i]; break;
            case N_DIM:                bias = (const float*)d_in[i]; break;
            case (K_DIM / 8) * N_DIM:  assign = (const int*)d_in[i]; break;
            default: break;
        }
    }

    static bool attr_done = false;
    if (!attr_done) {
        cudaFuncSetAttribute(gemm_kernel,
                             cudaFuncAttributeMaxDynamicSharedMemorySize, SMEM_TOTAL);
        attr_done = true;
    }

    prep_kernel<<<3072, 256>>>(x, assign, cent);
    gemm_kernel<<<dim3(NTILE_N, M_DIM / BM), THREADS, SMEM_TOTAL>>>(
        bias, (float*)d_out);
}